// round 17
// baseline (speedup 1.0000x reference)
#include <cuda_runtime.h>
#include <cuda_fp16.h>
#include <mma.h>
#include <float.h>
#include <stdint.h>

using namespace nvcuda;

#define NTOK 4096
#define DEMB 1024
#define NH   8
#define DH   128
#define CWW  256
#define QK_SCALE 0.08838834764831845f  // 1/sqrt(128)

// ---------------- scratch (static device memory; no allocations) ------------
__device__ float4 g_q4[NTOK * DH / 4];
__device__ float4 g_k4[NTOK * DH / 4];
__device__ float4 g_v4[NTOK * DH / 4];
__device__ float4 g_av4[NTOK * DH / 4];
__device__ float4 g_delta4[NTOK * DEMB / 4];

// ---------------- split-fp16 wmma GEMM + register prefetch ------------------
// C[64 rows, 128 cols] per CTA: C[n][m] = sum_k A[n][k]*B[m][k].
// Near-fp32 via fp16 hi/lo splits: Ah*Bh + Ah*Bl + Al*Bh, fp32 accumulators.
// Chunk t+1's gmem loads are issued before chunk t's MMAs (latency hiding).
#define SST 48

template <int K>
__device__ __forceinline__ void wmma_gemm_f32(
    const float* __restrict__ Ag,   // pre-offset: + n0*K
    const float* __restrict__ Bg,   // pre-offset: + m0*K (128 rows)
    float* __restrict__ C, int CS)  // pre-offset: + n0*CS + m0
{
    __shared__ __align__(32) __half sm[18432];  // 36 KB static
    __half* const sAh = sm;                     // 64 x 48
    __half* const sAl = sm + 3072;              // 64 x 48
    __half* const sBh = sm + 6144;              // 128 x 48
    __half* const sBl = sm + 12288;             // 128 x 48

    const int tid = threadIdx.x;
    const int wid = tid >> 5;
    const int wm  = (wid & 1) * 32;
    const int wn  = (wid >> 1) * 32;

    const int ar  = tid >> 2;          // A row 0..63
    const int akq = (tid & 3) * 8;     // A col offset 0,8,16,24
    const int br0 = tid >> 1;          // unused helper (kept simple below)

    wmma::fragment<wmma::accumulator, 16, 16, 16, float> acc[2][2];
#pragma unroll
    for (int mt = 0; mt < 2; mt++)
#pragma unroll
        for (int nt = 0; nt < 2; nt++) wmma::fill_fragment(acc[mt][nt], 0.0f);

    float4 fa0, fa1;        // A prefetch: 8 floats
    float4 fb[2][2];        // B prefetch: 2 rows x 8 floats

    // helper lambdas (inlined by compiler)
    auto load_regs = [&](int kc) {
        const float* asrc = Ag + (size_t)ar * K + kc + akq;
        fa0 = *(const float4*)asrc;
        fa1 = *(const float4*)(asrc + 4);
#pragma unroll
        for (int v = 0; v < 2; v++) {
            int idx = v * 256 + tid;
            int r   = idx >> 2;
            int kq  = (idx & 3) * 8;
            const float* bsrc = Bg + (size_t)r * K + kc + kq;
            fb[v][0] = *(const float4*)bsrc;
            fb[v][1] = *(const float4*)(bsrc + 4);
        }
    };
    auto store_smem = [&]() {
        {
            float fa[8] = {fa0.x, fa0.y, fa0.z, fa0.w, fa1.x, fa1.y, fa1.z, fa1.w};
            __half hh[8], ll[8];
#pragma unroll
            for (int q = 0; q < 8; q++) {
                hh[q] = __float2half_rn(fa[q]);
                ll[q] = __float2half_rn(fa[q] - __half2float(hh[q]));
            }
            *(uint4*)(sAh + ar * SST + akq) = *(uint4*)hh;
            *(uint4*)(sAl + ar * SST + akq) = *(uint4*)ll;
        }
#pragma unroll
        for (int v = 0; v < 2; v++) {
            int idx = v * 256 + tid;
            int r   = idx >> 2;
            int kq  = (idx & 3) * 8;
            float fbv[8] = {fb[v][0].x, fb[v][0].y, fb[v][0].z, fb[v][0].w,
                            fb[v][1].x, fb[v][1].y, fb[v][1].z, fb[v][1].w};
            __half hh[8], ll[8];
#pragma unroll
            for (int q = 0; q < 8; q++) {
                hh[q] = __float2half_rn(fbv[q]);
                ll[q] = __float2half_rn(fbv[q] - __half2float(hh[q]));
            }
            *(uint4*)(sBh + r * SST + kq) = *(uint4*)hh;
            *(uint4*)(sBl + r * SST + kq) = *(uint4*)ll;
        }
    };

    // prologue: chunk 0
    load_regs(0);
    store_smem();
    __syncthreads();

#pragma unroll 1
    for (int kc = 0; kc < K; kc += 32) {
        const bool has_next = (kc + 32) < K;
        if (has_next) load_regs(kc + 32);   // gmem loads overlap MMAs below

#pragma unroll
        for (int ks = 0; ks < 2; ks++) {
            wmma::fragment<wmma::matrix_a, 16, 16, 16, __half, wmma::row_major> ah[2], al[2];
            wmma::fragment<wmma::matrix_b, 16, 16, 16, __half, wmma::col_major> bh[2], bl[2];
#pragma unroll
            for (int mt = 0; mt < 2; mt++) {
                wmma::load_matrix_sync(ah[mt], sAh + (wm + mt * 16) * SST + ks * 16, SST);
                wmma::load_matrix_sync(al[mt], sAl + (wm + mt * 16) * SST + ks * 16, SST);
            }
#pragma unroll
            for (int nt = 0; nt < 2; nt++) {
                wmma::load_matrix_sync(bh[nt], sBh + (wn + nt * 16) * SST + ks * 16, SST);
                wmma::load_matrix_sync(bl[nt], sBl + (wn + nt * 16) * SST + ks * 16, SST);
            }
#pragma unroll
            for (int mt = 0; mt < 2; mt++)
#pragma unroll
                for (int nt = 0; nt < 2; nt++) {
                    wmma::mma_sync(acc[mt][nt], ah[mt], bh[nt], acc[mt][nt]);
                    wmma::mma_sync(acc[mt][nt], ah[mt], bl[nt], acc[mt][nt]);
                    wmma::mma_sync(acc[mt][nt], al[mt], bh[nt], acc[mt][nt]);
                }
        }
        if (has_next) {
            __syncthreads();   // all MMAs done reading smem
            store_smem();      // publish chunk t+1
            __syncthreads();
        }
    }

#pragma unroll
    for (int mt = 0; mt < 2; mt++)
#pragma unroll
        for (int nt = 0; nt < 2; nt++)
            wmma::store_matrix_sync(C + (size_t)(wm + mt * 16) * CS + wn + nt * 16,
                                    acc[mt][nt], CS, wmma::mem_row_major);
}

// QKV: grid (64, 3). q/k/vd = e @ W[h]^T, K=1024, C stride 128.
__global__ void __launch_bounds__(256) k_gemm_qkv(const float* __restrict__ e,
                                                  const float* __restrict__ Wq,
                                                  const float* __restrict__ Wk,
                                                  const float* __restrict__ Wvd) {
    const int n0 = blockIdx.x * 64;
    const int sel = blockIdx.y;
    const float* B = (sel == 0) ? Wq : (sel == 1 ? Wk : Wvd);
    float* C = (sel == 0) ? (float*)g_q4 : (sel == 1 ? (float*)g_k4 : (float*)g_v4);
    wmma_gemm_f32<DEMB>(e + (size_t)n0 * DEMB, B, C + (size_t)n0 * DH, DH);
}

// out projection: grid (64, 8). delta = av @ Wvu[h]^T, K=128, C stride 1024.
__global__ void __launch_bounds__(256) k_gemm_out(const float* __restrict__ Wvu) {
    const int n0 = blockIdx.x * 64;
    const int m0 = blockIdx.y * 128;
    wmma_gemm_f32<DH>((const float*)g_av4 + (size_t)n0 * DH,
                      Wvu + (size_t)m0 * DH,
                      (float*)g_delta4 + (size_t)n0 * DEMB + m0, DEMB);
}

// ---------------- banded attention (online softmax, fp32 SIMT; R12-proven) --
__global__ void __launch_bounds__(256) k_attn() {
    __shared__ float4 Qs[32 * 32];  // [q][d4]
    __shared__ float4 Kt[32 * 32];  // [d4][key ^ d4]
    __shared__ float4 Vs[32 * 32];  // [key][d4]
    const int tid  = threadIdx.x;
    const int lane = tid & 31;
    const int w    = tid >> 5;
    const int q0   = blockIdx.x * 32;

#pragma unroll
    for (int i = 0; i < 4; i++)
        Qs[tid + 256 * i] = g_q4[q0 * 32 + tid + 256 * i];

    float m[4], l[4];
    float4 o[4];
#pragma unroll
    for (int qi = 0; qi < 4; qi++) {
        m[qi] = -FLT_MAX;
        l[qi] = 0.f;
        o[qi] = make_float4(0.f, 0.f, 0.f, 0.f);
    }
    const int jbase = q0 + 4 * w;
    const int lo = (q0 >= CWW) ? (q0 - CWW) : 0;
    const int hi = min(q0 + 31 + CWW, NTOK);

    for (int kc = lo; kc < hi; kc += 32) {
        __syncthreads();
#pragma unroll
        for (int i = 0; i < 4; i++) {
            int idx = tid + 256 * i;
            int key = idx >> 5;
            int d4  = idx & 31;
            int kg  = kc + key;
            float4 kv = make_float4(0.f, 0.f, 0.f, 0.f);
            float4 vv = make_float4(0.f, 0.f, 0.f, 0.f);
            if (kg < NTOK) {
                kv = g_k4[kg * 32 + d4];
                vv = g_v4[kg * 32 + d4];
            }
            Kt[(d4 << 5) + (key ^ d4)] = kv;
            Vs[(key << 5) + d4] = vv;
        }
        __syncthreads();

        float s[4] = {0.f, 0.f, 0.f, 0.f};
#pragma unroll 8
        for (int d4 = 0; d4 < 32; d4++) {
            float4 kv = Kt[(d4 << 5) + (lane ^ d4)];
#pragma unroll
            for (int qi = 0; qi < 4; qi++) {
                float4 qv = Qs[(4 * w + qi) * 32 + d4];
                s[qi] += qv.x * kv.x + qv.y * kv.y + qv.z * kv.z + qv.w * kv.w;
            }
        }

        const int kg = kc + lane;
        float p[4];
#pragma unroll
        for (int qi = 0; qi < 4; qi++) {
            int j = jbase + qi;
            float sv = s[qi] * QK_SCALE;
            bool ok = (kg >= j - CWW) && (kg < j + CWW) && (kg < NTOK);
            sv = ok ? sv : -FLT_MAX;
            float c = sv;
#pragma unroll
            for (int off = 16; off; off >>= 1)
                c = fmaxf(c, __shfl_xor_sync(0xffffffffu, c, off));
            float mn   = fmaxf(m[qi], c);
            float corr = __expf(m[qi] - mn);
            float pv   = __expf(sv - mn);
            float su = pv;
#pragma unroll
            for (int off = 16; off; off >>= 1)
                su += __shfl_xor_sync(0xffffffffu, su, off);
            l[qi] = l[qi] * corr + su;
            m[qi] = mn;
            o[qi].x *= corr; o[qi].y *= corr; o[qi].z *= corr; o[qi].w *= corr;
            p[qi] = pv;
        }

#pragma unroll 4
        for (int k = 0; k < 32; k++) {
            float4 v = Vs[(k << 5) + lane];
#pragma unroll
            for (int qi = 0; qi < 4; qi++) {
                float wq = __shfl_sync(0xffffffffu, p[qi], k);
                o[qi].x += wq * v.x;
                o[qi].y += wq * v.y;
                o[qi].z += wq * v.z;
                o[qi].w += wq * v.w;
            }
        }
    }

#pragma unroll
    for (int qi = 0; qi < 4; qi++) {
        float r = 1.f / l[qi];
        g_av4[(jbase + qi) * 32 + lane] =
            make_float4(o[qi].x * r, o[qi].y * r, o[qi].z * r, o[qi].w * r);
    }
}

// ---------------- residual + norm (R3-proven; optional final 1/8 scale) -----
__device__ __forceinline__ float block_sum(float v, float* red) {
#pragma unroll
    for (int off = 16; off; off >>= 1) v += __shfl_xor_sync(0xffffffffu, v, off);
    if ((threadIdx.x & 31) == 0) red[threadIdx.x >> 5] = v;
    __syncthreads();
    float s = ((red[0] + red[1]) + (red[2] + red[3])) +
              ((red[4] + red[5]) + (red[6] + red[7]));
    __syncthreads();
    return s;
}

__global__ void __launch_bounds__(256) k_norm(float* __restrict__ e, float fin) {
    __shared__ float red[8];
    const int r = blockIdx.x;
    const int tid = threadIdx.x;
    const float* dl = (const float*)g_delta4;
    float ev[4], o[4];
    float s1 = 0.f;
#pragma unroll
    for (int i = 0; i < 4; i++) {
        int idx = r * DEMB + tid + 256 * i;
        ev[i] = e[idx];
        o[i]  = ev[i] + dl[idx];
        s1 += o[i];
    }
    s1 = block_sum(s1, red);
    float inv_mean1 = (float)DEMB / s1;           // out /= mean(out)
    float s2 = 0.f;
#pragma unroll
    for (int i = 0; i < 4; i++) {
        o[i] *= inv_mean1;
        s2 += o[i];
    }
    s2 = block_sum(s2, red);
    float mu = s2 * (1.0f / DEMB);
    float sq = 0.f;
#pragma unroll
    for (int i = 0; i < 4; i++) {
        float d = o[i] - mu;
        sq += d * d;
    }
    sq = block_sum(sq, red);
    float inv_sd = rsqrtf(sq * (1.0f / (DEMB - 1)));  // ddof=1
#pragma unroll
    for (int i = 0; i < 4; i++) {
        int idx = r * DEMB + tid + 256 * i;
        e[idx] = (ev[i] + (o[i] - mu) * inv_sd + mu) * fin;  // fin=0.125 exact pow2
    }
}

// ---------------- copy --------------------------------------------------------
__global__ void __launch_bounds__(256) k_copy(float4* __restrict__ dst,
                                              const float4* __restrict__ src) {
    int i = blockIdx.x * 256 + threadIdx.x;
    dst[i] = src[i];
}

// ---------------- launch -----------------------------------------------------
extern "C" void kernel_launch(void* const* d_in, const int* in_sizes, int n_in,
                              void* d_out, int out_size) {
    const float* x   = (const float*)d_in[0];
    const float* Wq  = (const float*)d_in[1];
    const float* Wk  = (const float*)d_in[2];
    const float* Wvd = (const float*)d_in[3];
    const float* Wvu = (const float*)d_in[4];
    float* e = (float*)d_out;

    k_copy<<<NTOK * DEMB / 4 / 256, 256>>>((float4*)e, (const float4*)x);
    for (int h = 0; h < NH; h++) {
        k_gemm_qkv<<<dim3(64, 3), 256>>>(e, Wq + (size_t)h * DH * DEMB,
                                         Wk + (size_t)h * DH * DEMB,
                                         Wvd + (size_t)h * DH * DEMB);
        k_attn<<<NTOK / 32, 256>>>();
        k_gemm_out<<<dim3(64, 8), 256>>>(Wvu + (size_t)h * DEMB * DH);
        k_norm<<<NTOK, 256>>>(e, (h == NH - 1) ? 0.125f : 1.0f);
    }
}